// round 13
// baseline (speedup 1.0000x reference)
#include <cuda_runtime.h>
#include <cuda_bf16.h>
#include <cstddef>
#include <cstdint>

#define SEQ   2048
#define BATCH 64
#define NIN   256
#define HID   256

#define HEAD_CHUNKS 320                 // chunks done by the full-chip head
#define PROJ_CHUNKS 1024                // 1 chunk = 128 m-rows = 2 timesteps
#define TAIL_START  HEAD_CHUNKS
#define TILES_PER_CHUNK 16              // (128/64 m) x (256/32 n)
#define NTAIL       148                 // persistent tail CTAs (1 per SM)

// Scratch
__device__ float g_xp[(size_t)SEQ * BATCH * HID];
__device__ __align__(16) int g_done[PROJ_CHUNKS];

// ---------------------------------------------------------------------------
// helpers
// ---------------------------------------------------------------------------
__device__ __forceinline__ uint32_t smem_u32(const void* p) {
    uint32_t a;
    asm("{ .reg .u64 t; cvta.to.shared.u64 t, %1; cvt.u32.u64 %0, t; }"
        : "=r"(a) : "l"(p));
    return a;
}

#define FMA2(acc, a, b)                                             \
    asm("fma.rn.f32x2 %0, %1, %2, %3;"                              \
        : "=l"(acc) : "l"(a), "l"(b), "l"(acc))

__device__ __forceinline__ unsigned long long pack_dup(float x) {
    unsigned long long d;
    asm("mov.b64 %0, {%1, %1};" : "=l"(d) : "r"(__float_as_uint(x)));
    return d;
}
__device__ __forceinline__ float2 unpack2(unsigned long long v) {
    float2 r;
    asm("mov.b64 {%0, %1}, %2;" : "=f"(r.x), "=f"(r.y) : "l"(v));
    return r;
}

__device__ __forceinline__ void mbar_wait(uint32_t mbar, uint32_t parity) {
    asm volatile(
        "{\n\t"
        ".reg .pred P;\n"
        "$WL%=:\n\t"
        "mbarrier.try_wait.parity.acquire.cta.shared::cta.b64 P, [%0], %1, 0x989680;\n\t"
        "@!P bra $WL%=;\n\t"
        "}"
        :: "r"(mbar), "r"(parity) : "memory");
}

__device__ __forceinline__ int4 ld_acquire_gpu_v4(const int4* p) {
    int4 v;
    asm volatile("ld.acquire.gpu.v4.b32 {%0,%1,%2,%3}, [%4];"
                 : "=r"(v.x), "=r"(v.y), "=r"(v.z), "=r"(v.w)
                 : "l"(p) : "memory");
    return v;
}

// fast tanh: 1 - 2/(e^{2x}+1), MUFU-based, ~1e-6 rel err, saturates correctly.
__device__ __forceinline__ float ftanh(float x) {
    float e = __expf(2.f * x);
    return 1.f - __fdividef(2.f, e + 1.f);
}

// ---------------------------------------------------------------------------
// Kernel 1: projection HEAD (f32x2, R2-proven body). grid (HEAD_CHUNKS, 4).
//   Block (0,0) additionally zeroes the tail-completion flags (readers and
//   writers of g_done all run in later kernels, so any head block may do it).
// ---------------------------------------------------------------------------
__global__ void __launch_bounds__(256) proj_kernel(
    const float* __restrict__ X,
    const float* __restrict__ W,
    const float* __restrict__ b_ih,
    const float* __restrict__ b_hh)
{
    constexpr int BM = 128, BN = 64, BK = 32;
    __shared__ float As[BK][BM + 4];
    __shared__ float Bs[BK][BN + 4];

    const int tid = threadIdx.x;

    if (blockIdx.x == 0 && blockIdx.y == 0) {
        for (int i = tid; i < PROJ_CHUNKS; i += 256) g_done[i] = 0;
        __threadfence();
    }

    const int m0  = blockIdx.x * BM;
    const int n0  = blockIdx.y * BN;
    const int tx  = tid & 15;
    const int ty  = tid >> 4;

    unsigned long long acc2[4][4];
#pragma unroll
    for (int i = 0; i < 4; i++)
#pragma unroll
        for (int j = 0; j < 4; j++) acc2[i][j] = 0ULL;

    for (int kb = 0; kb < NIN; kb += BK) {
#pragma unroll
        for (int it = 0; it < 4; it++) {
            int idx = tid + it * 256;
            int r   = idx >> 3;
            int c4  = idx & 7;
            float4 v = *(const float4*)&X[(size_t)(m0 + r) * NIN + kb + c4 * 4];
            As[c4 * 4 + 0][r] = v.x;
            As[c4 * 4 + 1][r] = v.y;
            As[c4 * 4 + 2][r] = v.z;
            As[c4 * 4 + 3][r] = v.w;
        }
#pragma unroll
        for (int it = 0; it < 2; it++) {
            int idx = tid + it * 256;
            int r   = idx >> 3;
            int c4  = idx & 7;
            float4 v = *(const float4*)&W[(size_t)(n0 + r) * NIN + kb + c4 * 4];
            Bs[c4 * 4 + 0][r] = v.x;
            Bs[c4 * 4 + 1][r] = v.y;
            Bs[c4 * 4 + 2][r] = v.z;
            Bs[c4 * 4 + 3][r] = v.w;
        }
        __syncthreads();

#pragma unroll
        for (int k = 0; k < BK; k++) {
            const ulonglong2* ap = (const ulonglong2*)&As[k][ty * 8];
            ulonglong2 av0 = ap[0];
            ulonglong2 av1 = ap[1];
            float4 bv = *(const float4*)&Bs[k][tx * 4];
            unsigned long long bd0 = pack_dup(bv.x);
            unsigned long long bd1 = pack_dup(bv.y);
            unsigned long long bd2 = pack_dup(bv.z);
            unsigned long long bd3 = pack_dup(bv.w);
            FMA2(acc2[0][0], av0.x, bd0); FMA2(acc2[0][1], av0.x, bd1);
            FMA2(acc2[0][2], av0.x, bd2); FMA2(acc2[0][3], av0.x, bd3);
            FMA2(acc2[1][0], av0.y, bd0); FMA2(acc2[1][1], av0.y, bd1);
            FMA2(acc2[1][2], av0.y, bd2); FMA2(acc2[1][3], av0.y, bd3);
            FMA2(acc2[2][0], av1.x, bd0); FMA2(acc2[2][1], av1.x, bd1);
            FMA2(acc2[2][2], av1.x, bd2); FMA2(acc2[2][3], av1.x, bd3);
            FMA2(acc2[3][0], av1.y, bd0); FMA2(acc2[3][1], av1.y, bd1);
            FMA2(acc2[3][2], av1.y, bd2); FMA2(acc2[3][3], av1.y, bd3);
        }
        __syncthreads();
    }

    const int nbase = n0 + tx * 4;
    float4 bias;
    bias.x = b_ih[nbase + 0] + b_hh[nbase + 0];
    bias.y = b_ih[nbase + 1] + b_hh[nbase + 1];
    bias.z = b_ih[nbase + 2] + b_hh[nbase + 2];
    bias.w = b_ih[nbase + 3] + b_hh[nbase + 3];
#pragma unroll
    for (int mi = 0; mi < 4; mi++) {
        float2 c0 = unpack2(acc2[mi][0]);
        float2 c1 = unpack2(acc2[mi][1]);
        float2 c2 = unpack2(acc2[mi][2]);
        float2 c3 = unpack2(acc2[mi][3]);
        int mA = m0 + ty * 8 + 2 * mi;
        float4 v0 = { c0.x + bias.x, c1.x + bias.y, c2.x + bias.z, c3.x + bias.w };
        float4 v1 = { c0.y + bias.x, c1.y + bias.y, c2.y + bias.z, c3.y + bias.w };
        *(float4*)&g_xp[(size_t)mA * HID + nbase]       = v0;
        *(float4*)&g_xp[(size_t)(mA + 1) * HID + nbase] = v1;
    }
}

// ---------------------------------------------------------------------------
// Kernel 2: persistent projection TAIL. 148 CTAs x 128 threads, <=73 regs
//   (launch_bounds(128,7)) so each CTA CO-RESIDES with an rnn CTA on the
//   same SM, harvesting the rnn's ~75% idle FMA issue. 64x32 tiles, BK=16.
//   CTA i processes tiles i, i+148, ... (ascending chunk order). Each
//   finished tile bumps g_done[chunk]; a chunk is complete at 16.
// ---------------------------------------------------------------------------
__global__ void __launch_bounds__(128, 7) tail_kernel(
    const float* __restrict__ X,
    const float* __restrict__ W,
    const float* __restrict__ b_ih,
    const float* __restrict__ b_hh)
{
    __shared__ float As[16][68];    // [k][m] 64 + pad
    __shared__ float Bs[16][36];    // [k][n] 32 + pad

    const int t  = threadIdx.x;
    const int tx = t & 7;           // n group: 4 wide
    const int ty = t >> 3;          // m group: 4 wide (16 groups)

    const int ntiles = (PROJ_CHUNKS - TAIL_START) * TILES_PER_CHUNK;

    for (int tile = blockIdx.x; tile < ntiles; tile += NTAIL) {
        const int chunk = TAIL_START + (tile >> 4);
        const int sub   = tile & 15;
        const int m0    = chunk * 128 + (sub >> 3) * 64;
        const int n0    = (sub & 7) * 32;

        float acc[4][4];
#pragma unroll
        for (int i = 0; i < 4; i++)
#pragma unroll
            for (int j = 0; j < 4; j++) acc[i][j] = 0.f;

        for (int kb = 0; kb < NIN; kb += 16) {
            // A tile: 64x16 = 256 float4 -> 2 per thread
#pragma unroll
            for (int it = 0; it < 2; it++) {
                int idx = t + it * 128;
                int r   = idx >> 2;
                int c4  = idx & 3;
                float4 v = *(const float4*)&X[(size_t)(m0 + r) * NIN + kb + c4 * 4];
                As[c4 * 4 + 0][r] = v.x;
                As[c4 * 4 + 1][r] = v.y;
                As[c4 * 4 + 2][r] = v.z;
                As[c4 * 4 + 3][r] = v.w;
            }
            // B tile: 32x16 = 128 float4 -> 1 per thread
            {
                int r  = t >> 2;
                int c4 = t & 3;
                float4 v = *(const float4*)&W[(size_t)(n0 + r) * NIN + kb + c4 * 4];
                Bs[c4 * 4 + 0][r] = v.x;
                Bs[c4 * 4 + 1][r] = v.y;
                Bs[c4 * 4 + 2][r] = v.z;
                Bs[c4 * 4 + 3][r] = v.w;
            }
            __syncthreads();
#pragma unroll
            for (int k = 0; k < 16; k++) {
                float a0 = As[k][ty * 4 + 0];
                float a1 = As[k][ty * 4 + 1];
                float a2 = As[k][ty * 4 + 2];
                float a3 = As[k][ty * 4 + 3];
                float b0 = Bs[k][tx * 4 + 0];
                float b1 = Bs[k][tx * 4 + 1];
                float b2 = Bs[k][tx * 4 + 2];
                float b3 = Bs[k][tx * 4 + 3];
                acc[0][0] = fmaf(a0, b0, acc[0][0]);
                acc[0][1] = fmaf(a0, b1, acc[0][1]);
                acc[0][2] = fmaf(a0, b2, acc[0][2]);
                acc[0][3] = fmaf(a0, b3, acc[0][3]);
                acc[1][0] = fmaf(a1, b0, acc[1][0]);
                acc[1][1] = fmaf(a1, b1, acc[1][1]);
                acc[1][2] = fmaf(a1, b2, acc[1][2]);
                acc[1][3] = fmaf(a1, b3, acc[1][3]);
                acc[2][0] = fmaf(a2, b0, acc[2][0]);
                acc[2][1] = fmaf(a2, b1, acc[2][1]);
                acc[2][2] = fmaf(a2, b2, acc[2][2]);
                acc[2][3] = fmaf(a2, b3, acc[2][3]);
                acc[3][0] = fmaf(a3, b0, acc[3][0]);
                acc[3][1] = fmaf(a3, b1, acc[3][1]);
                acc[3][2] = fmaf(a3, b2, acc[3][2]);
                acc[3][3] = fmaf(a3, b3, acc[3][3]);
            }
            __syncthreads();
        }

        // epilogue: bias + store
        const int nbase = n0 + tx * 4;
        float b0 = b_ih[nbase + 0] + b_hh[nbase + 0];
        float b1 = b_ih[nbase + 1] + b_hh[nbase + 1];
        float b2 = b_ih[nbase + 2] + b_hh[nbase + 2];
        float b3 = b_ih[nbase + 3] + b_hh[nbase + 3];
#pragma unroll
        for (int i = 0; i < 4; i++) {
            int m = m0 + ty * 4 + i;
            float4 v = { acc[i][0] + b0, acc[i][1] + b1,
                         acc[i][2] + b2, acc[i][3] + b3 };
            *(float4*)&g_xp[(size_t)m * HID + nbase] = v;
        }

        __syncthreads();
        if (t == 0) {
            __threadfence();
            atomicAdd(&g_done[chunk], 1);
        }
    }
}

// ---------------------------------------------------------------------------
// Kernel 3: recurrence — R2/R12-proven body + v4 flag gate + ftanh.
//   64 clusters x 2 CTAs, one batch per cluster, 0.55us/step.
// ---------------------------------------------------------------------------
__global__ void __launch_bounds__(256, 1) __cluster_dims__(2, 1, 1)
rnn_kernel(const float* __restrict__ W_hh, float* __restrict__ out)
{
    __shared__ float sm_h[2][256];
    __shared__ float sm_p[2][256];
    __shared__ __align__(8) unsigned long long sm_mbar[2];

    const int      t    = threadIdx.x;
    const uint32_t rank = blockIdx.x & 1;
    const int      b    = blockIdx.x >> 1;
    const int      k0   = rank << 7;

    unsigned long long w2[64];
    {
        const ulonglong2* wp = (const ulonglong2*)(W_hh + (size_t)t * HID + k0);
#pragma unroll
        for (int i = 0; i < 32; i++) {
            ulonglong2 v = wp[i];
            w2[2 * i]     = v.x;
            w2[2 * i + 1] = v.y;
        }
    }

    sm_h[0][t] = 0.f;
    if (t == 0) {
        asm volatile("mbarrier.init.shared.b64 [%0], 1;"
                     :: "r"(smem_u32(&sm_mbar[0])) : "memory");
        asm volatile("mbarrier.init.shared.b64 [%0], 1;"
                     :: "r"(smem_u32(&sm_mbar[1])) : "memory");
    }
    __syncthreads();
    asm volatile("barrier.cluster.arrive.aligned;" ::: "memory");
    asm volatile("barrier.cluster.wait.aligned;"   ::: "memory");

    const uint32_t peer  = rank ^ 1u;
    const uint32_t p_loc = smem_u32(&sm_p[0][0]);
    const uint32_t m_loc = smem_u32(&sm_mbar[0]);
    uint32_t p_rem, m_rem;
    asm("mapa.shared::cluster.u32 %0, %1, %2;"
        : "=r"(p_rem) : "r"(p_loc), "r"(peer));
    asm("mapa.shared::cluster.u32 %0, %1, %2;"
        : "=r"(m_rem) : "r"(m_loc), "r"(peer));

    // xp window (3 deep). Chunks 0..2 guaranteed by the head kernel.
    const float* xpb = g_xp + (size_t)b * HID + t;
    float xp0 = xpb[0];
    float xp1 = xpb[(size_t)1 * BATCH * HID];
    float xp2 = xpb[(size_t)2 * BATCH * HID];

    float* outp = out + (size_t)b * HID + t;
    const bool own = ((uint32_t)(t >> 7) == rank);
    int wm = HEAD_CHUNKS;                 // t0's flag watermark (tail only)

#pragma unroll 1
    for (int s = 0; s < SEQ; s++) {
        const uint32_t bufsel = (uint32_t)(s & 1);
        const uint32_t parity = (uint32_t)((s >> 1) & 1);

        // prefetch xp[s+3] (covered by the gate's 16-step lead)
        float xpn = 0.f;
        if (s + 3 < SEQ) xpn = xpb[(size_t)(s + 3) * BATCH * HID];

        // ---- dot over own k-half: 32 LDS.128 + 64 FFMA2 ----
        const ulonglong2* hp = (const ulonglong2*)(&sm_h[bufsel][0] + k0);
        unsigned long long a0 = 0ULL, a1 = 0ULL, a2 = 0ULL, a3 = 0ULL;
#pragma unroll
        for (int i = 0; i < 16; i++) {
            ulonglong2 h01 = hp[2 * i];
            ulonglong2 h23 = hp[2 * i + 1];
            FMA2(a0, w2[4 * i + 0], h01.x);
            FMA2(a1, w2[4 * i + 1], h01.y);
            FMA2(a2, w2[4 * i + 2], h23.x);
            FMA2(a3, w2[4 * i + 3], h23.y);
        }
        float2 f0 = unpack2(a0), f1 = unpack2(a1);
        float2 f2 = unpack2(a2), f3 = unpack2(a3);
        float mine = ((f0.x + f0.y) + (f1.x + f1.y))
                   + ((f2.x + f2.y) + (f3.x + f3.y));

        // ---- send partial to peer (R2-proven scalar st.async) ----
        asm volatile(
            "st.async.shared::cluster.mbarrier::complete_tx::bytes.b32 "
            "[%0], %1, [%2];"
            :: "r"(p_rem + (bufsel << 10) + ((uint32_t)t << 2)),
               "r"(__float_as_uint(mine)),
               "r"(m_rem + bufsel * 8)
            : "memory");

        if (t == 0) {
            asm volatile(
                "mbarrier.arrive.expect_tx.shared.b64 _, [%0], 1024;"
                :: "r"(m_loc + bufsel * 8) : "memory");
            // flag gate: keep 16-step lead, vectorized flag reads
            if ((s & 15) == 0) {
                int need = (s + 35) >> 1;
                if (need > PROJ_CHUNKS - 1) need = PROJ_CHUNKS - 1;
                while (wm <= need) {
                    int base = wm & ~3;
                    int4 v = ld_acquire_gpu_v4((const int4*)&g_done[base]);
                    int vals[4] = { v.x, v.y, v.z, v.w };
                    int c = wm;
                    while (c <= need && c < base + 4 &&
                           vals[c - base] >= TILES_PER_CHUNK) c++;
                    wm = c;           // if stale, loop re-loads (spin)
                }
            }
        }

        mbar_wait(m_loc + bufsel * 8, parity);

        // ---- combine (deterministic order), tanh, publish ----
        float theirs = sm_p[bufsel][t];
        float lo = rank ? theirs : mine;
        float hi = rank ? mine   : theirs;
        float hv = ftanh(xp0 + (lo + hi));
        if (own) {
            sm_h[bufsel ^ 1u][t] = hv;
            outp[(size_t)s * BATCH * HID] = hv;
        }

        xp0 = xp1; xp1 = xp2; xp2 = xpn;
        __syncthreads();
    }

    asm volatile("barrier.cluster.arrive.aligned;" ::: "memory");
    asm volatile("barrier.cluster.wait.aligned;"   ::: "memory");
}

// ---------------------------------------------------------------------------
extern "C" void kernel_launch(void* const* d_in, const int* in_sizes, int n_in,
                              void* d_out, int out_size)
{
    const float* input = (const float*)d_in[0];   // [SEQ, BATCH, NIN]
    const float* W_ih  = (const float*)d_in[1];   // [HID, NIN]
    const float* W_hh  = (const float*)d_in[2];   // [HID, HID]
    const float* b_ih  = (const float*)d_in[3];   // [HID]
    const float* b_hh  = (const float*)d_in[4];   // [HID]
    float* out = (float*)d_out;                   // [SEQ*BATCH, HID]

    // second stream + fork/join events (host objects only; no device memory)
    cudaStream_t s1;
    cudaStreamCreateWithFlags(&s1, cudaStreamNonBlocking);
    cudaEvent_t evA, evB;
    cudaEventCreateWithFlags(&evA, cudaEventDisableTiming);
    cudaEventCreateWithFlags(&evB, cudaEventDisableTiming);

    // 1) projection HEAD on the default stream (also zeroes g_done flags)
    dim3 hgrid(HEAD_CHUNKS, 4);
    proj_kernel<<<hgrid, 256>>>(input, W_ih, b_ih, b_hh);

    // 2) fork: persistent TAIL on s1, rnn on default — concurrent.
    cudaEventRecord(evA, 0);
    cudaStreamWaitEvent(s1, evA, 0);
    tail_kernel<<<NTAIL, 128, 0, s1>>>(input, W_ih, b_ih, b_hh);
    rnn_kernel<<<128, 256>>>(W_hh, out);

    // 3) join tail back into the default stream
    cudaEventRecord(evB, s1);
    cudaStreamWaitEvent(0, evB, 0);
}

// round 14
// speedup vs baseline: 1.1021x; 1.1021x over previous
#include <cuda_runtime.h>
#include <cuda_bf16.h>
#include <cstddef>
#include <cstdint>

#define SEQ   2048
#define BATCH 64
#define NIN   256
#define HID   256

#define RNN_BLOCKS  128                 // 64 clusters x 2 CTAs
#define HEAD_CHUNKS 448                 // chunks done by the head kernel
#define PROJ_CHUNKS 1024                // 1 chunk = 128 m-rows = 2 timesteps
#define TAIL_CHUNKS (PROJ_CHUNKS - HEAD_CHUNKS)        // 576
#define TOTAL_BLOCKS (RNN_BLOCKS + TAIL_CHUNKS * 4)    // 2432

// Scratch
__device__ float g_xp[(size_t)SEQ * BATCH * HID];
__device__ int   g_done[PROJ_CHUNKS];

// ---------------------------------------------------------------------------
// helpers
// ---------------------------------------------------------------------------
__device__ __forceinline__ uint32_t smem_u32(const void* p) {
    uint32_t a;
    asm("{ .reg .u64 t; cvta.to.shared.u64 t, %1; cvt.u32.u64 %0, t; }"
        : "=r"(a) : "l"(p));
    return a;
}

#define FMA2(acc, a, b)                                             \
    asm("fma.rn.f32x2 %0, %1, %2, %3;"                              \
        : "=l"(acc) : "l"(a), "l"(b), "l"(acc))

__device__ __forceinline__ unsigned long long pack_dup(float x) {
    unsigned long long d;
    asm("mov.b64 %0, {%1, %1};" : "=l"(d) : "r"(__float_as_uint(x)));
    return d;
}
__device__ __forceinline__ float2 unpack2(unsigned long long v) {
    float2 r;
    asm("mov.b64 {%0, %1}, %2;" : "=f"(r.x), "=f"(r.y) : "l"(v));
    return r;
}

__device__ __forceinline__ void mbar_wait(uint32_t mbar, uint32_t parity) {
    asm volatile(
        "{\n\t"
        ".reg .pred P;\n"
        "$WL%=:\n\t"
        "mbarrier.try_wait.parity.acquire.cta.shared::cta.b64 P, [%0], %1, 0x989680;\n\t"
        "@!P bra $WL%=;\n\t"
        "}"
        :: "r"(mbar), "r"(parity) : "memory");
}

__device__ __forceinline__ int ld_acquire_gpu(const int* p) {
    int v;
    asm volatile("ld.acquire.gpu.b32 %0, [%1];" : "=r"(v) : "l"(p) : "memory");
    return v;
}

// fast tanh: 1 - 2/(e^{2x}+1), MUFU-based, ~1e-6 rel err, saturates correctly.
__device__ __forceinline__ float ftanh(float x) {
    float e = __expf(2.f * x);
    return 1.f - __fdividef(2.f, e + 1.f);
}

// ---------------------------------------------------------------------------
// Kernel 1: projection HEAD (f32x2, R2-proven body). grid (HEAD_CHUNKS, 4).
//   Block (0,0) also zeroes the tail-completion flags (all g_done readers/
//   writers are in the fused kernel, which is stream-ordered after the head).
// ---------------------------------------------------------------------------
__global__ void __launch_bounds__(256) proj_kernel(
    const float* __restrict__ X,
    const float* __restrict__ W,
    const float* __restrict__ b_ih,
    const float* __restrict__ b_hh)
{
    constexpr int BM = 128, BN = 64, BK = 32;
    __shared__ float As[BK][BM + 4];
    __shared__ float Bs[BK][BN + 4];

    const int tid = threadIdx.x;

    if (blockIdx.x == 0 && blockIdx.y == 0) {
        for (int i = tid; i < PROJ_CHUNKS; i += 256) g_done[i] = 0;
        __threadfence();
    }

    const int m0  = blockIdx.x * BM;
    const int n0  = blockIdx.y * BN;
    const int tx  = tid & 15;
    const int ty  = tid >> 4;

    unsigned long long acc2[4][4];
#pragma unroll
    for (int i = 0; i < 4; i++)
#pragma unroll
        for (int j = 0; j < 4; j++) acc2[i][j] = 0ULL;

    for (int kb = 0; kb < NIN; kb += BK) {
#pragma unroll
        for (int it = 0; it < 4; it++) {
            int idx = tid + it * 256;
            int r   = idx >> 3;
            int c4  = idx & 7;
            float4 v = *(const float4*)&X[(size_t)(m0 + r) * NIN + kb + c4 * 4];
            As[c4 * 4 + 0][r] = v.x;
            As[c4 * 4 + 1][r] = v.y;
            As[c4 * 4 + 2][r] = v.z;
            As[c4 * 4 + 3][r] = v.w;
        }
#pragma unroll
        for (int it = 0; it < 2; it++) {
            int idx = tid + it * 256;
            int r   = idx >> 3;
            int c4  = idx & 7;
            float4 v = *(const float4*)&W[(size_t)(n0 + r) * NIN + kb + c4 * 4];
            Bs[c4 * 4 + 0][r] = v.x;
            Bs[c4 * 4 + 1][r] = v.y;
            Bs[c4 * 4 + 2][r] = v.z;
            Bs[c4 * 4 + 3][r] = v.w;
        }
        __syncthreads();

#pragma unroll
        for (int k = 0; k < BK; k++) {
            const ulonglong2* ap = (const ulonglong2*)&As[k][ty * 8];
            ulonglong2 av0 = ap[0];
            ulonglong2 av1 = ap[1];
            float4 bv = *(const float4*)&Bs[k][tx * 4];
            unsigned long long bd0 = pack_dup(bv.x);
            unsigned long long bd1 = pack_dup(bv.y);
            unsigned long long bd2 = pack_dup(bv.z);
            unsigned long long bd3 = pack_dup(bv.w);
            FMA2(acc2[0][0], av0.x, bd0); FMA2(acc2[0][1], av0.x, bd1);
            FMA2(acc2[0][2], av0.x, bd2); FMA2(acc2[0][3], av0.x, bd3);
            FMA2(acc2[1][0], av0.y, bd0); FMA2(acc2[1][1], av0.y, bd1);
            FMA2(acc2[1][2], av0.y, bd2); FMA2(acc2[1][3], av0.y, bd3);
            FMA2(acc2[2][0], av1.x, bd0); FMA2(acc2[2][1], av1.x, bd1);
            FMA2(acc2[2][2], av1.x, bd2); FMA2(acc2[2][3], av1.x, bd3);
            FMA2(acc2[3][0], av1.y, bd0); FMA2(acc2[3][1], av1.y, bd1);
            FMA2(acc2[3][2], av1.y, bd2); FMA2(acc2[3][3], av1.y, bd3);
        }
        __syncthreads();
    }

    const int nbase = n0 + tx * 4;
    float4 bias;
    bias.x = b_ih[nbase + 0] + b_hh[nbase + 0];
    bias.y = b_ih[nbase + 1] + b_hh[nbase + 1];
    bias.z = b_ih[nbase + 2] + b_hh[nbase + 2];
    bias.w = b_ih[nbase + 3] + b_hh[nbase + 3];
#pragma unroll
    for (int mi = 0; mi < 4; mi++) {
        float2 c0 = unpack2(acc2[mi][0]);
        float2 c1 = unpack2(acc2[mi][1]);
        float2 c2 = unpack2(acc2[mi][2]);
        float2 c3 = unpack2(acc2[mi][3]);
        int mA = m0 + ty * 8 + 2 * mi;
        float4 v0 = { c0.x + bias.x, c1.x + bias.y, c2.x + bias.z, c3.x + bias.w };
        float4 v1 = { c0.y + bias.x, c1.y + bias.y, c2.y + bias.z, c3.y + bias.w };
        *(float4*)&g_xp[(size_t)mA * HID + nbase]       = v0;
        *(float4*)&g_xp[(size_t)(mA + 1) * HID + nbase] = v1;
    }
}

// ---------------------------------------------------------------------------
// Kernel 2 (fused): R12-proven structure.
//   blocks [0,128): the R2 rnn (64 clusters x 2 CTAs) + t0 flag gate;
//     ONLY body change vs R12: ftanh replaces tanhf in the combine.
//   blocks [128, TOTAL): projection TAIL tiles for chunks [448,1024) on the
//     ~20 SMs the rnn leaves free (proven non-interfering in R12).
// ---------------------------------------------------------------------------
__global__ void __launch_bounds__(256, 1) __cluster_dims__(2, 1, 1)
fused_kernel(const float* __restrict__ X,
             const float* __restrict__ W_ih,
             const float* __restrict__ W_hh,
             const float* __restrict__ b_ih,
             const float* __restrict__ b_hh,
             float* __restrict__ out)
{
    __shared__ float sm_h[2][256];        // rnn: double-buffered h
    __shared__ float sm_p[2][256];        // rnn: peer partials
    __shared__ __align__(8) unsigned long long sm_mbar[2];
    __shared__ float sm_As[32][132];      // proj tail tiles
    __shared__ float sm_Bs[32][68];

    const int t = threadIdx.x;

    if (blockIdx.x >= RNN_BLOCKS) {
        // ===================== PROJECTION TAIL =====================
        const int pb    = blockIdx.x - RNN_BLOCKS;
        const int chunk = HEAD_CHUNKS + (pb >> 2);   // ascending completion
        const int ntile = pb & 3;
        const int m0    = chunk * 128;
        const int n0    = ntile * 64;
        const int tx    = t & 15;
        const int ty    = t >> 4;

        unsigned long long acc2[4][4];
#pragma unroll
        for (int i = 0; i < 4; i++)
#pragma unroll
            for (int j = 0; j < 4; j++) acc2[i][j] = 0ULL;

        for (int kb = 0; kb < NIN; kb += 32) {
#pragma unroll
            for (int it = 0; it < 4; it++) {
                int idx = t + it * 256;
                int r   = idx >> 3;
                int c4  = idx & 7;
                float4 v = *(const float4*)&X[(size_t)(m0 + r) * NIN + kb + c4 * 4];
                sm_As[c4 * 4 + 0][r] = v.x;
                sm_As[c4 * 4 + 1][r] = v.y;
                sm_As[c4 * 4 + 2][r] = v.z;
                sm_As[c4 * 4 + 3][r] = v.w;
            }
#pragma unroll
            for (int it = 0; it < 2; it++) {
                int idx = t + it * 256;
                int r   = idx >> 3;
                int c4  = idx & 7;
                float4 v = *(const float4*)&W_ih[(size_t)(n0 + r) * NIN + kb + c4 * 4];
                sm_Bs[c4 * 4 + 0][r] = v.x;
                sm_Bs[c4 * 4 + 1][r] = v.y;
                sm_Bs[c4 * 4 + 2][r] = v.z;
                sm_Bs[c4 * 4 + 3][r] = v.w;
            }
            __syncthreads();
#pragma unroll
            for (int k = 0; k < 32; k++) {
                const ulonglong2* ap = (const ulonglong2*)&sm_As[k][ty * 8];
                ulonglong2 av0 = ap[0];
                ulonglong2 av1 = ap[1];
                float4 bv = *(const float4*)&sm_Bs[k][tx * 4];
                unsigned long long bd0 = pack_dup(bv.x);
                unsigned long long bd1 = pack_dup(bv.y);
                unsigned long long bd2 = pack_dup(bv.z);
                unsigned long long bd3 = pack_dup(bv.w);
                FMA2(acc2[0][0], av0.x, bd0); FMA2(acc2[0][1], av0.x, bd1);
                FMA2(acc2[0][2], av0.x, bd2); FMA2(acc2[0][3], av0.x, bd3);
                FMA2(acc2[1][0], av0.y, bd0); FMA2(acc2[1][1], av0.y, bd1);
                FMA2(acc2[1][2], av0.y, bd2); FMA2(acc2[1][3], av0.y, bd3);
                FMA2(acc2[2][0], av1.x, bd0); FMA2(acc2[2][1], av1.x, bd1);
                FMA2(acc2[2][2], av1.x, bd2); FMA2(acc2[2][3], av1.x, bd3);
                FMA2(acc2[3][0], av1.y, bd0); FMA2(acc2[3][1], av1.y, bd1);
                FMA2(acc2[3][2], av1.y, bd2); FMA2(acc2[3][3], av1.y, bd3);
            }
            __syncthreads();
        }

        const int nbase = n0 + tx * 4;
        float4 bias;
        bias.x = b_ih[nbase + 0] + b_hh[nbase + 0];
        bias.y = b_ih[nbase + 1] + b_hh[nbase + 1];
        bias.z = b_ih[nbase + 2] + b_hh[nbase + 2];
        bias.w = b_ih[nbase + 3] + b_hh[nbase + 3];
#pragma unroll
        for (int mi = 0; mi < 4; mi++) {
            float2 c0 = unpack2(acc2[mi][0]);
            float2 c1 = unpack2(acc2[mi][1]);
            float2 c2 = unpack2(acc2[mi][2]);
            float2 c3 = unpack2(acc2[mi][3]);
            int mA = m0 + ty * 8 + 2 * mi;
            float4 v0 = { c0.x + bias.x, c1.x + bias.y, c2.x + bias.z, c3.x + bias.w };
            float4 v1 = { c0.y + bias.x, c1.y + bias.y, c2.y + bias.z, c3.y + bias.w };
            *(float4*)&g_xp[(size_t)mA * HID + nbase]       = v0;
            *(float4*)&g_xp[(size_t)(mA + 1) * HID + nbase] = v1;
        }

        __syncthreads();
        if (t == 0) {
            __threadfence();
            atomicAdd(&g_done[chunk], 1);
        }
        return;
    }

    // ===================== RECURRENCE (R2/R12 verbatim + ftanh) ============
    const uint32_t rank = blockIdx.x & 1;
    const int      b    = blockIdx.x >> 1;
    const int      k0   = rank << 7;

    unsigned long long w2[64];
    {
        const ulonglong2* wp = (const ulonglong2*)(W_hh + (size_t)t * HID + k0);
#pragma unroll
        for (int i = 0; i < 32; i++) {
            ulonglong2 v = wp[i];
            w2[2 * i]     = v.x;
            w2[2 * i + 1] = v.y;
        }
    }

    sm_h[0][t] = 0.f;
    if (t == 0) {
        asm volatile("mbarrier.init.shared.b64 [%0], 1;"
                     :: "r"(smem_u32(&sm_mbar[0])) : "memory");
        asm volatile("mbarrier.init.shared.b64 [%0], 1;"
                     :: "r"(smem_u32(&sm_mbar[1])) : "memory");
    }
    __syncthreads();
    asm volatile("barrier.cluster.arrive.aligned;" ::: "memory");
    asm volatile("barrier.cluster.wait.aligned;"   ::: "memory");

    const uint32_t peer  = rank ^ 1u;
    const uint32_t p_loc = smem_u32(&sm_p[0][0]);
    const uint32_t m_loc = smem_u32(&sm_mbar[0]);
    uint32_t p_rem, m_rem;
    asm("mapa.shared::cluster.u32 %0, %1, %2;"
        : "=r"(p_rem) : "r"(p_loc), "r"(peer));
    asm("mapa.shared::cluster.u32 %0, %1, %2;"
        : "=r"(m_rem) : "r"(m_loc), "r"(peer));

    // xp window (3 deep). Chunks 0..2 guaranteed by the head kernel.
    const float* xpb = g_xp + (size_t)b * HID + t;
    float xp0 = xpb[0];
    float xp1 = xpb[(size_t)1 * BATCH * HID];
    float xp2 = xpb[(size_t)2 * BATCH * HID];

    float* outp = out + (size_t)b * HID + t;
    const bool own = ((uint32_t)(t >> 7) == rank);
    int wm = HEAD_CHUNKS;                 // t0's flag watermark (tail only)

#pragma unroll 1
    for (int s = 0; s < SEQ; s++) {
        const uint32_t bufsel = (uint32_t)(s & 1);
        const uint32_t parity = (uint32_t)((s >> 1) & 1);

        // prefetch xp[s+3] (covered by the gate's 16-step lead)
        float xpn = 0.f;
        if (s + 3 < SEQ) xpn = xpb[(size_t)(s + 3) * BATCH * HID];

        // ---- dot over own k-half: 32 LDS.128 + 64 FFMA2 ----
        const ulonglong2* hp = (const ulonglong2*)(&sm_h[bufsel][0] + k0);
        unsigned long long a0 = 0ULL, a1 = 0ULL, a2 = 0ULL, a3 = 0ULL;
#pragma unroll
        for (int i = 0; i < 16; i++) {
            ulonglong2 h01 = hp[2 * i];
            ulonglong2 h23 = hp[2 * i + 1];
            FMA2(a0, w2[4 * i + 0], h01.x);
            FMA2(a1, w2[4 * i + 1], h01.y);
            FMA2(a2, w2[4 * i + 2], h23.x);
            FMA2(a3, w2[4 * i + 3], h23.y);
        }
        float2 f0 = unpack2(a0), f1 = unpack2(a1);
        float2 f2 = unpack2(a2), f3 = unpack2(a3);
        float mine = ((f0.x + f0.y) + (f1.x + f1.y))
                   + ((f2.x + f2.y) + (f3.x + f3.y));

        // ---- send partial to peer (all 256 threads; R2-proven) ----
        asm volatile(
            "st.async.shared::cluster.mbarrier::complete_tx::bytes.b32 "
            "[%0], %1, [%2];"
            :: "r"(p_rem + (bufsel << 10) + ((uint32_t)t << 2)),
               "r"(__float_as_uint(mine)),
               "r"(m_rem + bufsel * 8)
            : "memory");

        if (t == 0) {
            asm volatile(
                "mbarrier.arrive.expect_tx.shared.b64 _, [%0], 1024;"
                :: "r"(m_loc + bufsel * 8) : "memory");
            // flag gate: keep 16-step lead over the xp prefetches (tail only)
            if ((s & 15) == 0) {
                int need = (s + 35) >> 1;
                if (need > PROJ_CHUNKS - 1) need = PROJ_CHUNKS - 1;
                while (wm <= need) {
                    if (ld_acquire_gpu(&g_done[wm]) >= 4) wm++;
                }
            }
        }

        mbar_wait(m_loc + bufsel * 8, parity);

        // ---- combine (deterministic order), ftanh, publish ----
        float theirs = sm_p[bufsel][t];
        float lo = rank ? theirs : mine;
        float hi = rank ? mine   : theirs;
        float hv = ftanh(xp0 + (lo + hi));
        if (own) {
            sm_h[bufsel ^ 1u][t] = hv;
            outp[(size_t)s * BATCH * HID] = hv;
        }

        xp0 = xp1; xp1 = xp2; xp2 = xpn;
        __syncthreads();
    }

    asm volatile("barrier.cluster.arrive.aligned;" ::: "memory");
    asm volatile("barrier.cluster.wait.aligned;"   ::: "memory");
}

// ---------------------------------------------------------------------------
extern "C" void kernel_launch(void* const* d_in, const int* in_sizes, int n_in,
                              void* d_out, int out_size)
{
    const float* input = (const float*)d_in[0];   // [SEQ, BATCH, NIN]
    const float* W_ih  = (const float*)d_in[1];   // [HID, NIN]
    const float* W_hh  = (const float*)d_in[2];   // [HID, HID]
    const float* b_ih  = (const float*)d_in[3];   // [HID]
    const float* b_hh  = (const float*)d_in[4];   // [HID]
    float* out = (float*)d_out;                   // [SEQ*BATCH, HID]

    // 1) projection HEAD: chunks [0, 448) full chip; block(0,0) zeroes flags
    dim3 hgrid(HEAD_CHUNKS, 4);
    proj_kernel<<<hgrid, 256>>>(input, W_ih, b_ih, b_hh);

    // 2) fused: rnn (128 CTAs, 64 clusters) + projection TAIL (chunks 448..1023)
    fused_kernel<<<TOTAL_BLOCKS, 256>>>(input, W_ih, W_hh, b_ih, b_hh, out);
}

// round 15
// speedup vs baseline: 1.4148x; 1.2837x over previous
#include <cuda_runtime.h>
#include <cuda_bf16.h>
#include <cstddef>
#include <cstdint>

#define SEQ   2048
#define BATCH 64
#define NIN   256
#define HID   256

#define HEAD_CHUNKS 720                 // chunks done by the head kernel
#define PROJ_CHUNKS 1024                // 1 chunk = 128 m-rows = 2 timesteps
#define TAIL_CHUNKS (PROJ_CHUNKS - HEAD_CHUNKS)        // 304
#define TAIL_BLOCKS (TAIL_CHUNKS * 4)                  // 1216

// Scratch
__device__ float g_xp[(size_t)SEQ * BATCH * HID];
__device__ int   g_done[PROJ_CHUNKS];

// ---------------------------------------------------------------------------
// helpers
// ---------------------------------------------------------------------------
__device__ __forceinline__ uint32_t smem_u32(const void* p) {
    uint32_t a;
    asm("{ .reg .u64 t; cvta.to.shared.u64 t, %1; cvt.u32.u64 %0, t; }"
        : "=r"(a) : "l"(p));
    return a;
}

#define FMA2(acc, a, b)                                             \
    asm("fma.rn.f32x2 %0, %1, %2, %3;"                              \
        : "=l"(acc) : "l"(a), "l"(b), "l"(acc))

__device__ __forceinline__ unsigned long long pack_dup(float x) {
    unsigned long long d;
    asm("mov.b64 %0, {%1, %1};" : "=l"(d) : "r"(__float_as_uint(x)));
    return d;
}
__device__ __forceinline__ float2 unpack2(unsigned long long v) {
    float2 r;
    asm("mov.b64 {%0, %1}, %2;" : "=f"(r.x), "=f"(r.y) : "l"(v));
    return r;
}

__device__ __forceinline__ void mbar_wait(uint32_t mbar, uint32_t parity) {
    asm volatile(
        "{\n\t"
        ".reg .pred P;\n"
        "$WL%=:\n\t"
        "mbarrier.try_wait.parity.acquire.cta.shared::cta.b64 P, [%0], %1, 0x989680;\n\t"
        "@!P bra $WL%=;\n\t"
        "}"
        :: "r"(mbar), "r"(parity) : "memory");
}

__device__ __forceinline__ int ld_acquire_gpu(const int* p) {
    int v;
    asm volatile("ld.acquire.gpu.b32 %0, [%1];" : "=r"(v) : "l"(p) : "memory");
    return v;
}

// fast tanh: 1 - 2/(e^{2x}+1), MUFU-based, ~1e-6 rel err, saturates correctly.
__device__ __forceinline__ float ftanh(float x) {
    float e = __expf(2.f * x);
    return 1.f - __fdividef(2.f, e + 1.f);
}

// ---------------------------------------------------------------------------
// Shared proj-tile body (BM=128, BN=64, BK=32, 256 thr, f32x2) — R2-proven.
// ---------------------------------------------------------------------------
__device__ __forceinline__ void proj_tile_body(
    const float* __restrict__ X,
    const float* __restrict__ W,
    const float* __restrict__ b_ih,
    const float* __restrict__ b_hh,
    int m0, int n0, int tid,
    float (*As)[132], float (*Bs)[68])
{
    unsigned long long acc2[4][4];
#pragma unroll
    for (int i = 0; i < 4; i++)
#pragma unroll
        for (int j = 0; j < 4; j++) acc2[i][j] = 0ULL;

    const int tx = tid & 15;
    const int ty = tid >> 4;

    for (int kb = 0; kb < NIN; kb += 32) {
#pragma unroll
        for (int it = 0; it < 4; it++) {
            int idx = tid + it * 256;
            int r   = idx >> 3;
            int c4  = idx & 7;
            float4 v = *(const float4*)&X[(size_t)(m0 + r) * NIN + kb + c4 * 4];
            As[c4 * 4 + 0][r] = v.x;
            As[c4 * 4 + 1][r] = v.y;
            As[c4 * 4 + 2][r] = v.z;
            As[c4 * 4 + 3][r] = v.w;
        }
#pragma unroll
        for (int it = 0; it < 2; it++) {
            int idx = tid + it * 256;
            int r   = idx >> 3;
            int c4  = idx & 7;
            float4 v = *(const float4*)&W[(size_t)(n0 + r) * NIN + kb + c4 * 4];
            Bs[c4 * 4 + 0][r] = v.x;
            Bs[c4 * 4 + 1][r] = v.y;
            Bs[c4 * 4 + 2][r] = v.z;
            Bs[c4 * 4 + 3][r] = v.w;
        }
        __syncthreads();

#pragma unroll
        for (int k = 0; k < 32; k++) {
            const ulonglong2* ap = (const ulonglong2*)&As[k][ty * 8];
            ulonglong2 av0 = ap[0];
            ulonglong2 av1 = ap[1];
            float4 bv = *(const float4*)&Bs[k][tx * 4];
            unsigned long long bd0 = pack_dup(bv.x);
            unsigned long long bd1 = pack_dup(bv.y);
            unsigned long long bd2 = pack_dup(bv.z);
            unsigned long long bd3 = pack_dup(bv.w);
            FMA2(acc2[0][0], av0.x, bd0); FMA2(acc2[0][1], av0.x, bd1);
            FMA2(acc2[0][2], av0.x, bd2); FMA2(acc2[0][3], av0.x, bd3);
            FMA2(acc2[1][0], av0.y, bd0); FMA2(acc2[1][1], av0.y, bd1);
            FMA2(acc2[1][2], av0.y, bd2); FMA2(acc2[1][3], av0.y, bd3);
            FMA2(acc2[2][0], av1.x, bd0); FMA2(acc2[2][1], av1.x, bd1);
            FMA2(acc2[2][2], av1.x, bd2); FMA2(acc2[2][3], av1.x, bd3);
            FMA2(acc2[3][0], av1.y, bd0); FMA2(acc2[3][1], av1.y, bd1);
            FMA2(acc2[3][2], av1.y, bd2); FMA2(acc2[3][3], av1.y, bd3);
        }
        __syncthreads();
    }

    const int nbase = n0 + tx * 4;
    float4 bias;
    bias.x = b_ih[nbase + 0] + b_hh[nbase + 0];
    bias.y = b_ih[nbase + 1] + b_hh[nbase + 1];
    bias.z = b_ih[nbase + 2] + b_hh[nbase + 2];
    bias.w = b_ih[nbase + 3] + b_hh[nbase + 3];
#pragma unroll
    for (int mi = 0; mi < 4; mi++) {
        float2 c0 = unpack2(acc2[mi][0]);
        float2 c1 = unpack2(acc2[mi][1]);
        float2 c2 = unpack2(acc2[mi][2]);
        float2 c3 = unpack2(acc2[mi][3]);
        int mA = m0 + ty * 8 + 2 * mi;
        float4 v0 = { c0.x + bias.x, c1.x + bias.y, c2.x + bias.z, c3.x + bias.w };
        float4 v1 = { c0.y + bias.x, c1.y + bias.y, c2.y + bias.z, c3.y + bias.w };
        *(float4*)&g_xp[(size_t)mA * HID + nbase]       = v0;
        *(float4*)&g_xp[(size_t)(mA + 1) * HID + nbase] = v1;
    }
}

// ---------------------------------------------------------------------------
// Kernel 1: projection HEAD. grid (HEAD_CHUNKS, 4). Block (0,0) zeroes the
//   tail flags (all g_done readers/writers are stream-ordered after).
// ---------------------------------------------------------------------------
__global__ void __launch_bounds__(256) head_kernel(
    const float* __restrict__ X,
    const float* __restrict__ W,
    const float* __restrict__ b_ih,
    const float* __restrict__ b_hh)
{
    __shared__ float As[32][132];
    __shared__ float Bs[32][68];
    const int tid = threadIdx.x;

    if (blockIdx.x == 0 && blockIdx.y == 0) {
        for (int i = tid; i < PROJ_CHUNKS; i += 256) g_done[i] = 0;
        __threadfence();
    }
    proj_tile_body(X, W, b_ih, b_hh,
                   blockIdx.x * 128, blockIdx.y * 64, tid, As, Bs);
}

// ---------------------------------------------------------------------------
// Kernel 2: projection TAIL — separate NON-clustered kernel on a forked
//   stream. 256 thr, ~74 regs -> 18944 regs/CTA: CANNOT co-reside with an
//   rnn CTA (only ~10K regs free there), packs 3/SM on the rnn-free SMs.
//   Chunk order ascending; each finished tile bumps g_done[chunk] (4 = done).
// ---------------------------------------------------------------------------
__global__ void __launch_bounds__(256) tail_kernel(
    const float* __restrict__ X,
    const float* __restrict__ W,
    const float* __restrict__ b_ih,
    const float* __restrict__ b_hh)
{
    __shared__ float As[32][132];
    __shared__ float Bs[32][68];
    const int tid   = threadIdx.x;
    const int chunk = HEAD_CHUNKS + ((int)blockIdx.x >> 2);
    const int ntile = blockIdx.x & 3;

    proj_tile_body(X, W, b_ih, b_hh, chunk * 128, ntile * 64, tid, As, Bs);

    __syncthreads();
    if (tid == 0) {
        __threadfence();
        atomicAdd(&g_done[chunk], 1);
    }
}

// ---------------------------------------------------------------------------
// Kernel 3: recurrence — R2/R12-proven body; only change: ftanh.
//   64 clusters x 2 CTAs, one batch per cluster, t0 flag gate for the tail.
// ---------------------------------------------------------------------------
__global__ void __launch_bounds__(256, 1) __cluster_dims__(2, 1, 1)
rnn_kernel(const float* __restrict__ W_hh, float* __restrict__ out)
{
    __shared__ float sm_h[2][256];
    __shared__ float sm_p[2][256];
    __shared__ __align__(8) unsigned long long sm_mbar[2];

    const int      t    = threadIdx.x;
    const uint32_t rank = blockIdx.x & 1;
    const int      b    = blockIdx.x >> 1;
    const int      k0   = rank << 7;

    unsigned long long w2[64];
    {
        const ulonglong2* wp = (const ulonglong2*)(W_hh + (size_t)t * HID + k0);
#pragma unroll
        for (int i = 0; i < 32; i++) {
            ulonglong2 v = wp[i];
            w2[2 * i]     = v.x;
            w2[2 * i + 1] = v.y;
        }
    }

    sm_h[0][t] = 0.f;
    if (t == 0) {
        asm volatile("mbarrier.init.shared.b64 [%0], 1;"
                     :: "r"(smem_u32(&sm_mbar[0])) : "memory");
        asm volatile("mbarrier.init.shared.b64 [%0], 1;"
                     :: "r"(smem_u32(&sm_mbar[1])) : "memory");
    }
    __syncthreads();
    asm volatile("barrier.cluster.arrive.aligned;" ::: "memory");
    asm volatile("barrier.cluster.wait.aligned;"   ::: "memory");

    const uint32_t peer  = rank ^ 1u;
    const uint32_t p_loc = smem_u32(&sm_p[0][0]);
    const uint32_t m_loc = smem_u32(&sm_mbar[0]);
    uint32_t p_rem, m_rem;
    asm("mapa.shared::cluster.u32 %0, %1, %2;"
        : "=r"(p_rem) : "r"(p_loc), "r"(peer));
    asm("mapa.shared::cluster.u32 %0, %1, %2;"
        : "=r"(m_rem) : "r"(m_loc), "r"(peer));

    // xp window (3 deep). Chunks 0..2 guaranteed by the head kernel.
    const float* xpb = g_xp + (size_t)b * HID + t;
    float xp0 = xpb[0];
    float xp1 = xpb[(size_t)1 * BATCH * HID];
    float xp2 = xpb[(size_t)2 * BATCH * HID];

    float* outp = out + (size_t)b * HID + t;
    const bool own = ((uint32_t)(t >> 7) == rank);
    int wm = HEAD_CHUNKS;                 // t0's flag watermark (tail only)

#pragma unroll 1
    for (int s = 0; s < SEQ; s++) {
        const uint32_t bufsel = (uint32_t)(s & 1);
        const uint32_t parity = (uint32_t)((s >> 1) & 1);

        // prefetch xp[s+3] (covered by the gate's 16-step lead)
        float xpn = 0.f;
        if (s + 3 < SEQ) xpn = xpb[(size_t)(s + 3) * BATCH * HID];

        // ---- dot over own k-half: 32 LDS.128 + 64 FFMA2 ----
        const ulonglong2* hp = (const ulonglong2*)(&sm_h[bufsel][0] + k0);
        unsigned long long a0 = 0ULL, a1 = 0ULL, a2 = 0ULL, a3 = 0ULL;
#pragma unroll
        for (int i = 0; i < 16; i++) {
            ulonglong2 h01 = hp[2 * i];
            ulonglong2 h23 = hp[2 * i + 1];
            FMA2(a0, w2[4 * i + 0], h01.x);
            FMA2(a1, w2[4 * i + 1], h01.y);
            FMA2(a2, w2[4 * i + 2], h23.x);
            FMA2(a3, w2[4 * i + 3], h23.y);
        }
        float2 f0 = unpack2(a0), f1 = unpack2(a1);
        float2 f2 = unpack2(a2), f3 = unpack2(a3);
        float mine = ((f0.x + f0.y) + (f1.x + f1.y))
                   + ((f2.x + f2.y) + (f3.x + f3.y));

        // ---- send partial to peer (all 256 threads; R2-proven) ----
        asm volatile(
            "st.async.shared::cluster.mbarrier::complete_tx::bytes.b32 "
            "[%0], %1, [%2];"
            :: "r"(p_rem + (bufsel << 10) + ((uint32_t)t << 2)),
               "r"(__float_as_uint(mine)),
               "r"(m_rem + bufsel * 8)
            : "memory");

        if (t == 0) {
            asm volatile(
                "mbarrier.arrive.expect_tx.shared.b64 _, [%0], 1024;"
                :: "r"(m_loc + bufsel * 8) : "memory");
            // flag gate: keep 16-step lead over the xp prefetches (tail only)
            if ((s & 15) == 0) {
                int need = (s + 35) >> 1;
                if (need > PROJ_CHUNKS - 1) need = PROJ_CHUNKS - 1;
                while (wm <= need) {
                    if (ld_acquire_gpu(&g_done[wm]) >= 4) wm++;
                }
            }
        }

        mbar_wait(m_loc + bufsel * 8, parity);

        // ---- combine (deterministic order), ftanh, publish ----
        float theirs = sm_p[bufsel][t];
        float lo = rank ? theirs : mine;
        float hi = rank ? mine   : theirs;
        float hv = ftanh(xp0 + (lo + hi));
        if (own) {
            sm_h[bufsel ^ 1u][t] = hv;
            outp[(size_t)s * BATCH * HID] = hv;
        }

        xp0 = xp1; xp1 = xp2; xp2 = xpn;
        __syncthreads();
    }

    asm volatile("barrier.cluster.arrive.aligned;" ::: "memory");
    asm volatile("barrier.cluster.wait.aligned;"   ::: "memory");
}

// ---------------------------------------------------------------------------
extern "C" void kernel_launch(void* const* d_in, const int* in_sizes, int n_in,
                              void* d_out, int out_size)
{
    const float* input = (const float*)d_in[0];   // [SEQ, BATCH, NIN]
    const float* W_ih  = (const float*)d_in[1];   // [HID, NIN]
    const float* W_hh  = (const float*)d_in[2];   // [HID, HID]
    const float* b_ih  = (const float*)d_in[3];   // [HID]
    const float* b_hh  = (const float*)d_in[4];   // [HID]
    float* out = (float*)d_out;                   // [SEQ*BATCH, HID]

    // second stream + fork/join events (host objects only; R13-proven capture)
    cudaStream_t s1;
    cudaStreamCreateWithFlags(&s1, cudaStreamNonBlocking);
    cudaEvent_t evA, evB;
    cudaEventCreateWithFlags(&evA, cudaEventDisableTiming);
    cudaEventCreateWithFlags(&evB, cudaEventDisableTiming);

    // 1) projection HEAD on stream 0 (block(0,0) also zeroes g_done)
    dim3 hgrid(HEAD_CHUNKS, 4);
    head_kernel<<<hgrid, 256>>>(input, W_ih, b_ih, b_hh);

    // 2) fork: non-clustered TAIL on s1 (cannot co-reside with rnn CTAs by
    //    register arithmetic: 18944 regs/CTA > ~10K free on rnn SMs),
    //    rnn on stream 0 — concurrent.
    cudaEventRecord(evA, 0);
    cudaStreamWaitEvent(s1, evA, 0);
    tail_kernel<<<TAIL_BLOCKS, 256, 0, s1>>>(input, W_ih, b_ih, b_hh);
    rnn_kernel<<<128, 256>>>(W_hh, out);

    // 3) join tail back into stream 0
    cudaEventRecord(evB, s1);
    cudaStreamWaitEvent(0, evB, 0);
}

// round 16
// speedup vs baseline: 1.5485x; 1.0945x over previous
#include <cuda_runtime.h>
#include <cuda_bf16.h>
#include <cstddef>
#include <cstdint>

#define SEQ   2048
#define BATCH 64
#define NIN   256
#define HID   256

#define RNN_BLOCKS  128                 // 64 clusters x 2 CTAs
#define HEAD_CHUNKS 720                 // chunks done by the head kernel
#define PROJ_CHUNKS 1024                // 1 chunk = 128 m-rows = 2 timesteps
#define TAIL_CHUNKS (PROJ_CHUNKS - HEAD_CHUNKS)        // 304
#define TOTAL_BLOCKS (RNN_BLOCKS + TAIL_CHUNKS * 4)    // 1344

// Scratch
__device__ float g_xp[(size_t)SEQ * BATCH * HID];
__device__ int   g_done[PROJ_CHUNKS];

// ---------------------------------------------------------------------------
// helpers
// ---------------------------------------------------------------------------
__device__ __forceinline__ uint32_t smem_u32(const void* p) {
    uint32_t a;
    asm("{ .reg .u64 t; cvta.to.shared.u64 t, %1; cvt.u32.u64 %0, t; }"
        : "=r"(a) : "l"(p));
    return a;
}

#define FMA2(acc, a, b)                                             \
    asm("fma.rn.f32x2 %0, %1, %2, %3;"                              \
        : "=l"(acc) : "l"(a), "l"(b), "l"(acc))

__device__ __forceinline__ unsigned long long pack_dup(float x) {
    unsigned long long d;
    asm("mov.b64 %0, {%1, %1};" : "=l"(d) : "r"(__float_as_uint(x)));
    return d;
}
__device__ __forceinline__ float2 unpack2(unsigned long long v) {
    float2 r;
    asm("mov.b64 {%0, %1}, %2;" : "=f"(r.x), "=f"(r.y) : "l"(v));
    return r;
}

__device__ __forceinline__ void mbar_wait(uint32_t mbar, uint32_t parity) {
    asm volatile(
        "{\n\t"
        ".reg .pred P;\n"
        "$WL%=:\n\t"
        "mbarrier.try_wait.parity.acquire.cta.shared::cta.b64 P, [%0], %1, 0x989680;\n\t"
        "@!P bra $WL%=;\n\t"
        "}"
        :: "r"(mbar), "r"(parity) : "memory");
}

__device__ __forceinline__ int ld_acquire_gpu(const int* p) {
    int v;
    asm volatile("ld.acquire.gpu.b32 %0, [%1];" : "=r"(v) : "l"(p) : "memory");
    return v;
}

// fast tanh: 1 - 2/(e^{2x}+1), MUFU-based, ~1e-6 rel err, saturates correctly.
__device__ __forceinline__ float ftanh(float x) {
    float e = __expf(2.f * x);
    return 1.f - __fdividef(2.f, e + 1.f);
}

// ---------------------------------------------------------------------------
// Kernel 1: projection HEAD (f32x2, R2-proven body). grid (HEAD_CHUNKS, 4).
//   Block (0,0) also zeroes the tail-completion flags (all g_done readers/
//   writers are in the fused kernel, stream-ordered after the head).
// ---------------------------------------------------------------------------
__global__ void __launch_bounds__(256) proj_kernel(
    const float* __restrict__ X,
    const float* __restrict__ W,
    const float* __restrict__ b_ih,
    const float* __restrict__ b_hh)
{
    constexpr int BM = 128, BN = 64, BK = 32;
    __shared__ float As[BK][BM + 4];
    __shared__ float Bs[BK][BN + 4];

    const int tid = threadIdx.x;

    if (blockIdx.x == 0 && blockIdx.y == 0) {
        for (int i = tid; i < PROJ_CHUNKS; i += 256) g_done[i] = 0;
        __threadfence();
    }

    const int m0  = blockIdx.x * BM;
    const int n0  = blockIdx.y * BN;
    const int tx  = tid & 15;
    const int ty  = tid >> 4;

    unsigned long long acc2[4][4];
#pragma unroll
    for (int i = 0; i < 4; i++)
#pragma unroll
        for (int j = 0; j < 4; j++) acc2[i][j] = 0ULL;

    for (int kb = 0; kb < NIN; kb += BK) {
#pragma unroll
        for (int it = 0; it < 4; it++) {
            int idx = tid + it * 256;
            int r   = idx >> 3;
            int c4  = idx & 7;
            float4 v = *(const float4*)&X[(size_t)(m0 + r) * NIN + kb + c4 * 4];
            As[c4 * 4 + 0][r] = v.x;
            As[c4 * 4 + 1][r] = v.y;
            As[c4 * 4 + 2][r] = v.z;
            As[c4 * 4 + 3][r] = v.w;
        }
#pragma unroll
        for (int it = 0; it < 2; it++) {
            int idx = tid + it * 256;
            int r   = idx >> 3;
            int c4  = idx & 7;
            float4 v = *(const float4*)&W[(size_t)(n0 + r) * NIN + kb + c4 * 4];
            Bs[c4 * 4 + 0][r] = v.x;
            Bs[c4 * 4 + 1][r] = v.y;
            Bs[c4 * 4 + 2][r] = v.z;
            Bs[c4 * 4 + 3][r] = v.w;
        }
        __syncthreads();

#pragma unroll
        for (int k = 0; k < BK; k++) {
            const ulonglong2* ap = (const ulonglong2*)&As[k][ty * 8];
            ulonglong2 av0 = ap[0];
            ulonglong2 av1 = ap[1];
            float4 bv = *(const float4*)&Bs[k][tx * 4];
            unsigned long long bd0 = pack_dup(bv.x);
            unsigned long long bd1 = pack_dup(bv.y);
            unsigned long long bd2 = pack_dup(bv.z);
            unsigned long long bd3 = pack_dup(bv.w);
            FMA2(acc2[0][0], av0.x, bd0); FMA2(acc2[0][1], av0.x, bd1);
            FMA2(acc2[0][2], av0.x, bd2); FMA2(acc2[0][3], av0.x, bd3);
            FMA2(acc2[1][0], av0.y, bd0); FMA2(acc2[1][1], av0.y, bd1);
            FMA2(acc2[1][2], av0.y, bd2); FMA2(acc2[1][3], av0.y, bd3);
            FMA2(acc2[2][0], av1.x, bd0); FMA2(acc2[2][1], av1.x, bd1);
            FMA2(acc2[2][2], av1.x, bd2); FMA2(acc2[2][3], av1.x, bd3);
            FMA2(acc2[3][0], av1.y, bd0); FMA2(acc2[3][1], av1.y, bd1);
            FMA2(acc2[3][2], av1.y, bd2); FMA2(acc2[3][3], av1.y, bd3);
        }
        __syncthreads();
    }

    const int nbase = n0 + tx * 4;
    float4 bias;
    bias.x = b_ih[nbase + 0] + b_hh[nbase + 0];
    bias.y = b_ih[nbase + 1] + b_hh[nbase + 1];
    bias.z = b_ih[nbase + 2] + b_hh[nbase + 2];
    bias.w = b_ih[nbase + 3] + b_hh[nbase + 3];
#pragma unroll
    for (int mi = 0; mi < 4; mi++) {
        float2 c0 = unpack2(acc2[mi][0]);
        float2 c1 = unpack2(acc2[mi][1]);
        float2 c2 = unpack2(acc2[mi][2]);
        float2 c3 = unpack2(acc2[mi][3]);
        int mA = m0 + ty * 8 + 2 * mi;
        float4 v0 = { c0.x + bias.x, c1.x + bias.y, c2.x + bias.z, c3.x + bias.w };
        float4 v1 = { c0.y + bias.x, c1.y + bias.y, c2.y + bias.z, c3.y + bias.w };
        *(float4*)&g_xp[(size_t)mA * HID + nbase]       = v0;
        *(float4*)&g_xp[(size_t)(mA + 1) * HID + nbase] = v1;
    }
}

// ---------------------------------------------------------------------------
// Kernel 2 (fused): R12-proven champion structure, tuned.
//   blocks [0,128): the R2 rnn (64 clusters x 2 CTAs) + t0 flag gate;
//     only body change vs R12: ftanh replaces tanhf in the combine.
//   blocks [128, TOTAL): projection TAIL tiles for chunks [720,1024) on the
//     ~20 SMs the rnn leaves free (R12-proven non-interfering placement:
//     rnn blocks come first in the CLC map, tail fills what's left).
// ---------------------------------------------------------------------------
__global__ void __launch_bounds__(256, 1) __cluster_dims__(2, 1, 1)
fused_kernel(const float* __restrict__ X,
             const float* __restrict__ W_ih,
             const float* __restrict__ W_hh,
             const float* __restrict__ b_ih,
             const float* __restrict__ b_hh,
             float* __restrict__ out)
{
    __shared__ float sm_h[2][256];        // rnn: double-buffered h
    __shared__ float sm_p[2][256];        // rnn: peer partials
    __shared__ __align__(8) unsigned long long sm_mbar[2];
    __shared__ float sm_As[32][132];      // proj tail tiles
    __shared__ float sm_Bs[32][68];

    const int t = threadIdx.x;

    if (blockIdx.x >= RNN_BLOCKS) {
        // ===================== PROJECTION TAIL =====================
        const int pb    = blockIdx.x - RNN_BLOCKS;
        const int chunk = HEAD_CHUNKS + (pb >> 2);   // ascending completion
        const int ntile = pb & 3;
        const int m0    = chunk * 128;
        const int n0    = ntile * 64;
        const int tx    = t & 15;
        const int ty    = t >> 4;

        unsigned long long acc2[4][4];
#pragma unroll
        for (int i = 0; i < 4; i++)
#pragma unroll
            for (int j = 0; j < 4; j++) acc2[i][j] = 0ULL;

        for (int kb = 0; kb < NIN; kb += 32) {
#pragma unroll
            for (int it = 0; it < 4; it++) {
                int idx = t + it * 256;
                int r   = idx >> 3;
                int c4  = idx & 7;
                float4 v = *(const float4*)&X[(size_t)(m0 + r) * NIN + kb + c4 * 4];
                sm_As[c4 * 4 + 0][r] = v.x;
                sm_As[c4 * 4 + 1][r] = v.y;
                sm_As[c4 * 4 + 2][r] = v.z;
                sm_As[c4 * 4 + 3][r] = v.w;
            }
#pragma unroll
            for (int it = 0; it < 2; it++) {
                int idx = t + it * 256;
                int r   = idx >> 3;
                int c4  = idx & 7;
                float4 v = *(const float4*)&W_ih[(size_t)(n0 + r) * NIN + kb + c4 * 4];
                sm_Bs[c4 * 4 + 0][r] = v.x;
                sm_Bs[c4 * 4 + 1][r] = v.y;
                sm_Bs[c4 * 4 + 2][r] = v.z;
                sm_Bs[c4 * 4 + 3][r] = v.w;
            }
            __syncthreads();
#pragma unroll
            for (int k = 0; k < 32; k++) {
                const ulonglong2* ap = (const ulonglong2*)&sm_As[k][ty * 8];
                ulonglong2 av0 = ap[0];
                ulonglong2 av1 = ap[1];
                float4 bv = *(const float4*)&sm_Bs[k][tx * 4];
                unsigned long long bd0 = pack_dup(bv.x);
                unsigned long long bd1 = pack_dup(bv.y);
                unsigned long long bd2 = pack_dup(bv.z);
                unsigned long long bd3 = pack_dup(bv.w);
                FMA2(acc2[0][0], av0.x, bd0); FMA2(acc2[0][1], av0.x, bd1);
                FMA2(acc2[0][2], av0.x, bd2); FMA2(acc2[0][3], av0.x, bd3);
                FMA2(acc2[1][0], av0.y, bd0); FMA2(acc2[1][1], av0.y, bd1);
                FMA2(acc2[1][2], av0.y, bd2); FMA2(acc2[1][3], av0.y, bd3);
                FMA2(acc2[2][0], av1.x, bd0); FMA2(acc2[2][1], av1.x, bd1);
                FMA2(acc2[2][2], av1.x, bd2); FMA2(acc2[2][3], av1.x, bd3);
                FMA2(acc2[3][0], av1.y, bd0); FMA2(acc2[3][1], av1.y, bd1);
                FMA2(acc2[3][2], av1.y, bd2); FMA2(acc2[3][3], av1.y, bd3);
            }
            __syncthreads();
        }

        const int nbase = n0 + tx * 4;
        float4 bias;
        bias.x = b_ih[nbase + 0] + b_hh[nbase + 0];
        bias.y = b_ih[nbase + 1] + b_hh[nbase + 1];
        bias.z = b_ih[nbase + 2] + b_hh[nbase + 2];
        bias.w = b_ih[nbase + 3] + b_hh[nbase + 3];
#pragma unroll
        for (int mi = 0; mi < 4; mi++) {
            float2 c0 = unpack2(acc2[mi][0]);
            float2 c1 = unpack2(acc2[mi][1]);
            float2 c2 = unpack2(acc2[mi][2]);
            float2 c3 = unpack2(acc2[mi][3]);
            int mA = m0 + ty * 8 + 2 * mi;
            float4 v0 = { c0.x + bias.x, c1.x + bias.y, c2.x + bias.z, c3.x + bias.w };
            float4 v1 = { c0.y + bias.x, c1.y + bias.y, c2.y + bias.z, c3.y + bias.w };
            *(float4*)&g_xp[(size_t)mA * HID + nbase]       = v0;
            *(float4*)&g_xp[(size_t)(mA + 1) * HID + nbase] = v1;
        }

        __syncthreads();
        if (t == 0) {
            __threadfence();
            atomicAdd(&g_done[chunk], 1);
        }
        return;
    }

    // ===================== RECURRENCE (R2/R12 verbatim + ftanh) ============
    const uint32_t rank = blockIdx.x & 1;
    const int      b    = blockIdx.x >> 1;
    const int      k0   = rank << 7;

    unsigned long long w2[64];
    {
        const ulonglong2* wp = (const ulonglong2*)(W_hh + (size_t)t * HID + k0);
#pragma unroll
        for (int i = 0; i < 32; i++) {
            ulonglong2 v = wp[i];
            w2[2 * i]     = v.x;
            w2[2 * i + 1] = v.y;
        }
    }

    sm_h[0][t] = 0.f;
    if (t == 0) {
        asm volatile("mbarrier.init.shared.b64 [%0], 1;"
                     :: "r"(smem_u32(&sm_mbar[0])) : "memory");
        asm volatile("mbarrier.init.shared.b64 [%0], 1;"
                     :: "r"(smem_u32(&sm_mbar[1])) : "memory");
    }
    __syncthreads();
    asm volatile("barrier.cluster.arrive.aligned;" ::: "memory");
    asm volatile("barrier.cluster.wait.aligned;"   ::: "memory");

    const uint32_t peer  = rank ^ 1u;
    const uint32_t p_loc = smem_u32(&sm_p[0][0]);
    const uint32_t m_loc = smem_u32(&sm_mbar[0]);
    uint32_t p_rem, m_rem;
    asm("mapa.shared::cluster.u32 %0, %1, %2;"
        : "=r"(p_rem) : "r"(p_loc), "r"(peer));
    asm("mapa.shared::cluster.u32 %0, %1, %2;"
        : "=r"(m_rem) : "r"(m_loc), "r"(peer));

    // xp window (3 deep). Chunks 0..2 guaranteed by the head kernel.
    const float* xpb = g_xp + (size_t)b * HID + t;
    float xp0 = xpb[0];
    float xp1 = xpb[(size_t)1 * BATCH * HID];
    float xp2 = xpb[(size_t)2 * BATCH * HID];

    float* outp = out + (size_t)b * HID + t;
    const bool own = ((uint32_t)(t >> 7) == rank);
    int wm = HEAD_CHUNKS;                 // t0's flag watermark (tail only)

#pragma unroll 1
    for (int s = 0; s < SEQ; s++) {
        const uint32_t bufsel = (uint32_t)(s & 1);
        const uint32_t parity = (uint32_t)((s >> 1) & 1);

        // prefetch xp[s+3] (covered by the gate's 16-step lead)
        float xpn = 0.f;
        if (s + 3 < SEQ) xpn = xpb[(size_t)(s + 3) * BATCH * HID];

        // ---- dot over own k-half: 32 LDS.128 + 64 FFMA2 ----
        const ulonglong2* hp = (const ulonglong2*)(&sm_h[bufsel][0] + k0);
        unsigned long long a0 = 0ULL, a1 = 0ULL, a2 = 0ULL, a3 = 0ULL;
#pragma unroll
        for (int i = 0; i < 16; i++) {
            ulonglong2 h01 = hp[2 * i];
            ulonglong2 h23 = hp[2 * i + 1];
            FMA2(a0, w2[4 * i + 0], h01.x);
            FMA2(a1, w2[4 * i + 1], h01.y);
            FMA2(a2, w2[4 * i + 2], h23.x);
            FMA2(a3, w2[4 * i + 3], h23.y);
        }
        float2 f0 = unpack2(a0), f1 = unpack2(a1);
        float2 f2 = unpack2(a2), f3 = unpack2(a3);
        float mine = ((f0.x + f0.y) + (f1.x + f1.y))
                   + ((f2.x + f2.y) + (f3.x + f3.y));

        // ---- send partial to peer (all 256 threads; R2-proven) ----
        asm volatile(
            "st.async.shared::cluster.mbarrier::complete_tx::bytes.b32 "
            "[%0], %1, [%2];"
            :: "r"(p_rem + (bufsel << 10) + ((uint32_t)t << 2)),
               "r"(__float_as_uint(mine)),
               "r"(m_rem + bufsel * 8)
            : "memory");

        if (t == 0) {
            asm volatile(
                "mbarrier.arrive.expect_tx.shared.b64 _, [%0], 1024;"
                :: "r"(m_loc + bufsel * 8) : "memory");
            // flag gate: keep 16-step lead over the xp prefetches (tail only)
            if ((s & 15) == 0) {
                int need = (s + 35) >> 1;
                if (need > PROJ_CHUNKS - 1) need = PROJ_CHUNKS - 1;
                while (wm <= need) {
                    if (ld_acquire_gpu(&g_done[wm]) >= 4) wm++;
                }
            }
        }

        mbar_wait(m_loc + bufsel * 8, parity);

        // ---- combine (deterministic order), ftanh, publish ----
        float theirs = sm_p[bufsel][t];
        float lo = rank ? theirs : mine;
        float hi = rank ? mine   : theirs;
        float hv = ftanh(xp0 + (lo + hi));
        if (own) {
            sm_h[bufsel ^ 1u][t] = hv;
            outp[(size_t)s * BATCH * HID] = hv;
        }

        xp0 = xp1; xp1 = xp2; xp2 = xpn;
        __syncthreads();
    }

    asm volatile("barrier.cluster.arrive.aligned;" ::: "memory");
    asm volatile("barrier.cluster.wait.aligned;"   ::: "memory");
}

// ---------------------------------------------------------------------------
extern "C" void kernel_launch(void* const* d_in, const int* in_sizes, int n_in,
                              void* d_out, int out_size)
{
    const float* input = (const float*)d_in[0];   // [SEQ, BATCH, NIN]
    const float* W_ih  = (const float*)d_in[1];   // [HID, NIN]
    const float* W_hh  = (const float*)d_in[2];   // [HID, HID]
    const float* b_ih  = (const float*)d_in[3];   // [HID]
    const float* b_hh  = (const float*)d_in[4];   // [HID]
    float* out = (float*)d_out;                   // [SEQ*BATCH, HID]

    // 1) projection HEAD: chunks [0, 720) full chip; block(0,0) zeroes flags
    dim3 hgrid(HEAD_CHUNKS, 4);
    proj_kernel<<<hgrid, 256>>>(input, W_ih, b_ih, b_hh);

    // 2) fused: rnn (128 CTAs, 64 clusters, placed FIRST by the CLC map)
    //    + projection TAIL (chunks 720..1023) on the leftover ~20 SMs
    fused_kernel<<<TOTAL_BLOCKS, 256>>>(input, W_ih, W_hh, b_ih, b_hh, out);
}